// round 15
// baseline (speedup 1.0000x reference)
#include <cuda_runtime.h>
#include <math.h>
#include <cstdint>

// Problem sizes
#define Bv 256
#define Tv 512
#define Fv 512
#define Hv 512
#define FH 2048
#define NSTEPS 257   // layer1 steps 0..255; layer2 pipelined (batch b = s-1) steps 1..256
#define GRIDB 96

// ---------------- device scratch (no allocations allowed) ----------------
__device__ __align__(16) float gZ1[Bv * FH];     // x[:,T-1,:] @ Wi1 + b1
__device__ __align__(16) float gH1buf[2][Hv];    // double-buffered layer1 hidden
__device__ __align__(16) float gH2buf[2][Hv];    // double-buffered layer2 hidden
__device__ __align__(16) float gH2all[Bv * Hv];  // all layer2 outputs ("last" matrix)
__device__ int g_cnt;                            // grid barrier counter (monotonic per launch)

// fast gate math (MUFU EX2-based; validated at rel_err 6.5e-7 in R7/R10/R12)
__device__ __forceinline__ float sigf(float x)  { return 1.0f / (1.0f + __expf(-x)); }
__device__ __forceinline__ float tanhx(float x) { return 1.0f - 2.0f / (__expf(2.0f * x) + 1.0f); }

__device__ __forceinline__ int ld_acq(const int* p) {
    int v;
    asm volatile("ld.acquire.gpu.global.b32 %0, [%1];" : "=r"(v) : "l"(p));
    return v;
}
// release reduction: publishes all writes that happened-before (incl. via bar.sync)
__device__ __forceinline__ void red_rel_add(int* p, int v) {
    asm volatile("red.release.gpu.global.add.s32 [%0], %1;" :: "l"(p), "r"(v) : "memory");
}
__device__ __forceinline__ float ldcg(const float* p) {
    float v;
    asm volatile("ld.global.cg.f32 %0, [%1];" : "=f"(v) : "l"(p));
    return v;
}

// ---------------- init (fresh state every launch/replay) ----------------
__global__ void initK() {
    int t = threadIdx.x;
    for (int i = t; i < Hv; i += blockDim.x) {
        gH1buf[0][i] = 0.f; gH1buf[1][i] = 0.f;
        gH2buf[0][i] = 0.f; gH2buf[1][i] = 0.f;
    }
    if (t == 0) g_cnt = 0;
}

// ---------------- Phase A: Z1 = x[:,T-1,:] @ Wi1 + b1 ----------------
__global__ void gemmZ1(const float* __restrict__ x,
                       const float* __restrict__ Wi1,
                       const float* __restrict__ b1) {
    __shared__ __align__(16) float xs[8][512];
    const int tid = threadIdx.x;
    const int col = blockIdx.x * 1024 + tid * 4;
    const int b0  = blockIdx.y * 8;

    for (int i = tid; i < 8 * 512; i += 256) {
        int r = i >> 9, f = i & 511;
        xs[r][f] = x[(size_t)(b0 + r) * Tv * Fv + (size_t)(Tv - 1) * Fv + f];
    }
    __syncthreads();

    float4 acc[8];
    float4 bv = *(const float4*)(b1 + col);
    #pragma unroll
    for (int r = 0; r < 8; r++) acc[r] = bv;

    for (int k = 0; k < Fv; k++) {
        float4 w = *(const float4*)(Wi1 + (size_t)k * FH + col);
        #pragma unroll
        for (int r = 0; r < 8; r++) {
            float xv = xs[r][k];
            acc[r].x = fmaf(xv, w.x, acc[r].x);
            acc[r].y = fmaf(xv, w.y, acc[r].y);
            acc[r].z = fmaf(xv, w.z, acc[r].z);
            acc[r].w = fmaf(xv, w.w, acc[r].w);
        }
    }
    #pragma unroll
    for (int r = 0; r < 8; r++)
        *(float4*)&gZ1[(size_t)(b0 + r) * FH + col] = acc[r];
}

// ---------------- Phase B: persistent kernel (R14 clone; fast gates + zin prefetch) ----------------
// 96 blocks x 256 threads, all co-resident.
//   Blocks 0..31  : layer1, 16 units each (64 gate-cols), active for s < 256.
//   Blocks 32..95 : layer2, 8 units each (32 gate-cols), active for s >= 1.
// Weights register-resident; cell state in owning thread's register.
// Barrier identical to R14 (tied-best): bar -> tid0 red.release + ld.acquire spin -> bar.
// Deltas vs R14: (1) MUFU-based gates; (2) gZ1 row for step s+1 prefetched into a
// register before the barrier (overlaps arrive+spin instead of sitting post-dot).
__global__ void __launch_bounds__(256, 1) lstmPersist(
    const float* __restrict__ Wh1, const float* __restrict__ Wi2,
    const float* __restrict__ Wh2, const float* __restrict__ b2,
    const float* __restrict__ Wd,  const float* __restrict__ bd,
    float* __restrict__ out)
{
    __shared__ __align__(16) float sH[1024];
    __shared__ __align__(16) float sPart[1024];
    __shared__ float sZ[64];

    const int tid = threadIdx.x;
    const int bx  = blockIdx.x;

    if (bx < 32) {
        // ================= layer 1 =================
        const int u0 = bx * 16;
        const int cg = tid & 15;
        const int ks = tid >> 4;
        const int c0 = cg * 4;
        const int g  = c0 >> 4;
        const int col = g * Hv + u0 + (c0 & 15);
        const int kb  = ks * 32;

        float4 rw[32];
        {
            const float* Wp = Wh1 + (size_t)kb * FH + col;
            #pragma unroll
            for (int j = 0; j < 32; j++)
                rw[j] = *(const float4*)(Wp + (size_t)j * FH);
        }
        float cst = 0.f;   // cell state for unit u0+tid (tid<16)

        // reducer-thread gZ1 column (tid<64) + prefetch of step 0's z-input
        const int rcc = (tid >> 4) * Hv + u0 + (tid & 15);
        float zpre = (tid < 64) ? __ldg(gZ1 + rcc) : 0.f;

        for (int s = 0; s < NSTEPS; s++) {
            const int rb = s & 1, wb = rb ^ 1;
            if (s < Bv) {
                for (int i = tid; i < Hv; i += 256) sH[i] = ldcg(&gH1buf[rb][i]);
                __syncthreads();

                float4 a = make_float4(0.f, 0.f, 0.f, 0.f);
                #pragma unroll
                for (int j = 0; j < 32; j++) {
                    float hk = sH[kb + j];
                    a.x = fmaf(hk, rw[j].x, a.x); a.y = fmaf(hk, rw[j].y, a.y);
                    a.z = fmaf(hk, rw[j].z, a.z); a.w = fmaf(hk, rw[j].w, a.w);
                }
                *(float4*)&sPart[ks * 64 + c0] = a;
                __syncthreads();

                if (tid < 64) {
                    float z = 0.f;
                    #pragma unroll
                    for (int r = 0; r < 16; r++) z += sPart[r * 64 + tid];
                    sZ[tid] = z + zpre;
                }
                __syncthreads();

                if (tid < 16) {
                    const int u = u0 + tid;
                    float zi = sZ[tid], zf = sZ[16 + tid], zg = sZ[32 + tid], zo = sZ[48 + tid];
                    cst = sigf(zf) * cst + sigf(zi) * tanhx(zg);
                    gH1buf[wb][u] = sigf(zo) * tanhx(cst);
                }
                // prefetch next step's z-input; overlaps the barrier below
                if (tid < 64 && s + 1 < Bv)
                    zpre = __ldg(gZ1 + (size_t)(s + 1) * FH + rcc);
            }
            __syncthreads();   // h-stores happen-before tid0's release below
            if (tid == 0) {
                red_rel_add(&g_cnt, 1);
                const int target = GRIDB * (s + 1);
                while (ld_acq(&g_cnt) < target) { }
            }
            __syncthreads();   // release block; next step's ld.cg reads L2
        }
    } else {
        // ================= layer 2 =================
        const int u0 = (bx - 32) * 8;
        const int cg = tid & 7;
        const int ks = tid >> 3;
        const int c0 = cg * 4;
        const int g  = c0 >> 3;
        const int col = g * Hv + u0 + (c0 & 7);
        const int kb  = ks * 32;

        float4 rw[32];
        {
            const float* Wp = (kb < Hv ? Wi2 + (size_t)kb * FH
                                       : Wh2 + (size_t)(kb - Hv) * FH) + col;
            #pragma unroll
            for (int j = 0; j < 32; j++)
                rw[j] = *(const float4*)(Wp + (size_t)j * FH);
        }
        float b2r = 0.f;
        if (tid < 32) {
            const int gg = tid >> 3;
            b2r = b2[gg * Hv + u0 + (tid & 7)];
        }
        float cst = 0.f;   // cell state for unit u0+tid (tid<8)

        for (int s = 0; s < NSTEPS; s++) {
            const int rb = s & 1, wb = rb ^ 1;
            if (s >= 1) {
                for (int i = tid; i < Hv; i += 256) sH[i]      = ldcg(&gH1buf[rb][i]);
                for (int i = tid; i < Hv; i += 256) sH[Hv + i] = ldcg(&gH2buf[rb][i]);
                __syncthreads();

                float4 a = make_float4(0.f, 0.f, 0.f, 0.f);
                #pragma unroll
                for (int j = 0; j < 32; j++) {
                    float hk = sH[kb + j];
                    a.x = fmaf(hk, rw[j].x, a.x); a.y = fmaf(hk, rw[j].y, a.y);
                    a.z = fmaf(hk, rw[j].z, a.z); a.w = fmaf(hk, rw[j].w, a.w);
                }
                *(float4*)&sPart[ks * 32 + c0] = a;
                __syncthreads();

                if (tid < 32) {
                    float z = 0.f;
                    #pragma unroll
                    for (int r = 0; r < 32; r++) z += sPart[r * 32 + tid];
                    sZ[tid] = z + b2r;
                }
                __syncthreads();

                if (tid < 8) {
                    const int u = u0 + tid;
                    float zi = sZ[tid], zf = sZ[8 + tid], zg = sZ[16 + tid], zo = sZ[24 + tid];
                    cst = sigf(zf) * cst + sigf(zi) * tanhx(zg);
                    float h = sigf(zo) * tanhx(cst);
                    gH2buf[wb][u] = h;
                    gH2all[(size_t)(s - 1) * Hv + u] = h;
                }
            }
            __syncthreads();   // h-stores happen-before tid0's release below
            if (tid == 0) {
                red_rel_add(&g_cnt, 1);
                const int target = GRIDB * (s + 1);
                while (ld_acq(&g_cnt) < target) { }
            }
            __syncthreads();   // release block
        }
    }

    // ================= fused output GEMM: out = gH2all @ Wd + bd =================
    // Final barrier above (acquire of GRIDB*NSTEPS) guarantees gH2all complete & visible.
    const int w    = tid >> 5;
    const int lane = tid & 31;
    for (int m = bx; m < Bv; m += GRIDB) {
        for (int o = w; o < 10; o += 8) {
            float acc = 0.f;
            #pragma unroll
            for (int j = 0; j < 16; j++) {
                int k = lane * 16 + j;
                acc = fmaf(ldcg(&gH2all[(size_t)m * Hv + k]), __ldg(Wd + (size_t)k * 10 + o), acc);
            }
            #pragma unroll
            for (int off = 16; off; off >>= 1)
                acc += __shfl_xor_sync(0xffffffffu, acc, off);
            if (lane == 0) out[m * 10 + o] = acc + __ldg(bd + o);
        }
    }
}

// ---------------- launch ----------------
extern "C" void kernel_launch(void* const* d_in, const int* in_sizes, int n_in,
                              void* d_out, int out_size) {
    (void)in_sizes; (void)n_in; (void)out_size;
    const float* x   = (const float*)d_in[0];
    const float* Wi1 = (const float*)d_in[1];
    const float* Wh1 = (const float*)d_in[2];
    const float* b1  = (const float*)d_in[3];
    const float* Wi2 = (const float*)d_in[4];
    const float* Wh2 = (const float*)d_in[5];
    const float* b2  = (const float*)d_in[6];
    const float* Wd  = (const float*)d_in[7];
    const float* bd  = (const float*)d_in[8];
    float* out = (float*)d_out;

    initK<<<1, 256>>>();
    gemmZ1<<<dim3(2, 32), 256>>>(x, Wi1, b1);
    lstmPersist<<<GRIDB, 256>>>(Wh1, Wi2, Wh2, b2, Wd, bd, out);
}

// round 16
// speedup vs baseline: 1.0519x; 1.0519x over previous
#include <cuda_runtime.h>
#include <math.h>
#include <cstdint>

// Problem sizes
#define Bv 256
#define Tv 512
#define Fv 512
#define Hv 512
#define FH 2048
#define NSTEPS 257   // layer1 steps 0..255; layer2 pipelined (batch b = s-1) steps 1..256
#define GRIDB 96

// ---------------- device scratch (no allocations allowed) ----------------
__device__ __align__(16) float gZ1[Bv * FH];     // x[:,T-1,:] @ Wi1 + b1
__device__ __align__(16) float gH1buf[2][Hv];    // double-buffered layer1 hidden
__device__ __align__(16) float gH2buf[2][Hv];    // double-buffered layer2 hidden
__device__ __align__(16) float gH2all[Bv * Hv];  // all layer2 outputs ("last" matrix)
__device__ int g_cnt;                            // grid barrier counter (reset by gemmZ1)

__device__ __forceinline__ float sigf(float x) { return 1.0f / (1.0f + expf(-x)); }

__device__ __forceinline__ int ld_acq(const int* p) {
    int v;
    asm volatile("ld.acquire.gpu.global.b32 %0, [%1];" : "=r"(v) : "l"(p));
    return v;
}
// release reduction: publishes all writes that happened-before (incl. via bar.sync)
__device__ __forceinline__ void red_rel_add(int* p, int v) {
    asm volatile("red.release.gpu.global.add.s32 [%0], %1;" :: "l"(p), "r"(v) : "memory");
}
__device__ __forceinline__ float ldcg(const float* p) {
    float v;
    asm volatile("ld.global.cg.f32 %0, [%1];" : "=f"(v) : "l"(p));
    return v;
}

// ---------------- Phase A: Z1 = x[:,T-1,:] @ Wi1 + b1 (+ counter reset) ----------------
__global__ void gemmZ1(const float* __restrict__ x,
                       const float* __restrict__ Wi1,
                       const float* __restrict__ b1) {
    // per-launch barrier-counter reset (stream-ordered before lstmPersist)
    if (blockIdx.x == 0 && blockIdx.y == 0 && threadIdx.x == 0) g_cnt = 0;

    __shared__ __align__(16) float xs[8][512];
    const int tid = threadIdx.x;
    const int col = blockIdx.x * 1024 + tid * 4;
    const int b0  = blockIdx.y * 8;

    for (int i = tid; i < 8 * 512; i += 256) {
        int r = i >> 9, f = i & 511;
        xs[r][f] = x[(size_t)(b0 + r) * Tv * Fv + (size_t)(Tv - 1) * Fv + f];
    }
    __syncthreads();

    float4 acc[8];
    float4 bv = *(const float4*)(b1 + col);
    #pragma unroll
    for (int r = 0; r < 8; r++) acc[r] = bv;

    for (int k = 0; k < Fv; k++) {
        float4 w = *(const float4*)(Wi1 + (size_t)k * FH + col);
        #pragma unroll
        for (int r = 0; r < 8; r++) {
            float xv = xs[r][k];
            acc[r].x = fmaf(xv, w.x, acc[r].x);
            acc[r].y = fmaf(xv, w.y, acc[r].y);
            acc[r].z = fmaf(xv, w.z, acc[r].z);
            acc[r].w = fmaf(xv, w.w, acc[r].w);
        }
    }
    #pragma unroll
    for (int r = 0; r < 8; r++)
        *(float4*)&gZ1[(size_t)(b0 + r) * FH + col] = acc[r];
}

// ---------------- Phase B: persistent kernel (exact R14 body; no initK needed) ----------------
// 96 blocks x 256 threads, all co-resident.
//   Blocks 0..31  : layer1, 16 units each (64 gate-cols), active for s < 256.
//   Blocks 32..95 : layer2, 8 units each (32 gate-cols), active for s >= 1.
// Weights register-resident (32 float4/thread); cell state in owning thread's register.
// Barrier (tied-best R14): bar -> tid0 red.release.gpu.add + ld.acquire spin -> bar.
// Zero-state boundary steps (s==0 layer1, s==1 layer2 h2) write zeros to smem
// directly instead of reading pre-zeroed global buffers (deletes initK).
__global__ void __launch_bounds__(256, 1) lstmPersist(
    const float* __restrict__ Wh1, const float* __restrict__ Wi2,
    const float* __restrict__ Wh2, const float* __restrict__ b2,
    const float* __restrict__ Wd,  const float* __restrict__ bd,
    float* __restrict__ out)
{
    __shared__ __align__(16) float sH[1024];
    __shared__ __align__(16) float sPart[1024];
    __shared__ float sZ[64];

    const int tid = threadIdx.x;
    const int bx  = blockIdx.x;

    if (bx < 32) {
        // ================= layer 1 =================
        const int u0 = bx * 16;
        const int cg = tid & 15;
        const int ks = tid >> 4;
        const int c0 = cg * 4;
        const int g  = c0 >> 4;
        const int col = g * Hv + u0 + (c0 & 15);
        const int kb  = ks * 32;

        float4 rw[32];
        {
            const float* Wp = Wh1 + (size_t)kb * FH + col;
            #pragma unroll
            for (int j = 0; j < 32; j++)
                rw[j] = *(const float4*)(Wp + (size_t)j * FH);
        }
        float cst = 0.f;   // cell state for unit u0+tid (tid<16)

        for (int s = 0; s < NSTEPS; s++) {
            const int rb = s & 1, wb = rb ^ 1;
            if (s < Bv) {
                if (s > 0) {
                    for (int i = tid; i < Hv; i += 256) sH[i] = ldcg(&gH1buf[rb][i]);
                } else {
                    for (int i = tid; i < Hv; i += 256) sH[i] = 0.f;   // h1[-1] = 0
                }
                __syncthreads();

                float4 a = make_float4(0.f, 0.f, 0.f, 0.f);
                #pragma unroll
                for (int j = 0; j < 32; j++) {
                    float hk = sH[kb + j];
                    a.x = fmaf(hk, rw[j].x, a.x); a.y = fmaf(hk, rw[j].y, a.y);
                    a.z = fmaf(hk, rw[j].z, a.z); a.w = fmaf(hk, rw[j].w, a.w);
                }
                *(float4*)&sPart[ks * 64 + c0] = a;
                __syncthreads();

                if (tid < 64) {
                    float z = 0.f;
                    #pragma unroll
                    for (int r = 0; r < 16; r++) z += sPart[r * 64 + tid];
                    const int gg = tid >> 4;
                    const int cc = gg * Hv + u0 + (tid & 15);
                    sZ[tid] = z + gZ1[(size_t)s * FH + cc];
                }
                __syncthreads();

                if (tid < 16) {
                    const int u = u0 + tid;
                    float zi = sZ[tid], zf = sZ[16 + tid], zg = sZ[32 + tid], zo = sZ[48 + tid];
                    cst = sigf(zf) * cst + sigf(zi) * tanhf(zg);
                    gH1buf[wb][u] = sigf(zo) * tanhf(cst);
                }
            }
            __syncthreads();   // h-stores happen-before tid0's release below
            if (tid == 0) {
                red_rel_add(&g_cnt, 1);
                const int target = GRIDB * (s + 1);
                while (ld_acq(&g_cnt) < target) { }
            }
            __syncthreads();   // release block; next step's ld.cg reads L2
        }
    } else {
        // ================= layer 2 =================
        const int u0 = (bx - 32) * 8;
        const int cg = tid & 7;
        const int ks = tid >> 3;
        const int c0 = cg * 4;
        const int g  = c0 >> 3;
        const int col = g * Hv + u0 + (c0 & 7);
        const int kb  = ks * 32;

        float4 rw[32];
        {
            const float* Wp = (kb < Hv ? Wi2 + (size_t)kb * FH
                                       : Wh2 + (size_t)(kb - Hv) * FH) + col;
            #pragma unroll
            for (int j = 0; j < 32; j++)
                rw[j] = *(const float4*)(Wp + (size_t)j * FH);
        }
        float b2r = 0.f;
        if (tid < 32) {
            const int gg = tid >> 3;
            b2r = b2[gg * Hv + u0 + (tid & 7)];
        }
        float cst = 0.f;   // cell state for unit u0+tid (tid<8)

        for (int s = 0; s < NSTEPS; s++) {
            const int rb = s & 1, wb = rb ^ 1;
            if (s >= 1) {
                for (int i = tid; i < Hv; i += 256) sH[i] = ldcg(&gH1buf[rb][i]);
                if (s >= 2) {
                    for (int i = tid; i < Hv; i += 256) sH[Hv + i] = ldcg(&gH2buf[rb][i]);
                } else {
                    for (int i = tid; i < Hv; i += 256) sH[Hv + i] = 0.f;   // h2[-1] = 0
                }
                __syncthreads();

                float4 a = make_float4(0.f, 0.f, 0.f, 0.f);
                #pragma unroll
                for (int j = 0; j < 32; j++) {
                    float hk = sH[kb + j];
                    a.x = fmaf(hk, rw[j].x, a.x); a.y = fmaf(hk, rw[j].y, a.y);
                    a.z = fmaf(hk, rw[j].z, a.z); a.w = fmaf(hk, rw[j].w, a.w);
                }
                *(float4*)&sPart[ks * 32 + c0] = a;
                __syncthreads();

                if (tid < 32) {
                    float z = 0.f;
                    #pragma unroll
                    for (int r = 0; r < 32; r++) z += sPart[r * 32 + tid];
                    sZ[tid] = z + b2r;
                }
                __syncthreads();

                if (tid < 8) {
                    const int u = u0 + tid;
                    float zi = sZ[tid], zf = sZ[8 + tid], zg = sZ[16 + tid], zo = sZ[24 + tid];
                    cst = sigf(zf) * cst + sigf(zi) * tanhf(zg);
                    float h = sigf(zo) * tanhf(cst);
                    gH2buf[wb][u] = h;
                    gH2all[(size_t)(s - 1) * Hv + u] = h;
                }
            }
            __syncthreads();   // h-stores happen-before tid0's release below
            if (tid == 0) {
                red_rel_add(&g_cnt, 1);
                const int target = GRIDB * (s + 1);
                while (ld_acq(&g_cnt) < target) { }
            }
            __syncthreads();   // release block
        }
    }

    // ================= fused output GEMM: out = gH2all @ Wd + bd =================
    // Final barrier above (acquire of GRIDB*NSTEPS) guarantees gH2all complete & visible.
    const int w    = tid >> 5;
    const int lane = tid & 31;
    for (int m = bx; m < Bv; m += GRIDB) {
        for (int o = w; o < 10; o += 8) {
            float acc = 0.f;
            #pragma unroll
            for (int j = 0; j < 16; j++) {
                int k = lane * 16 + j;
                acc = fmaf(ldcg(&gH2all[(size_t)m * Hv + k]), __ldg(Wd + (size_t)k * 10 + o), acc);
            }
            #pragma unroll
            for (int off = 16; off; off >>= 1)
                acc += __shfl_xor_sync(0xffffffffu, acc, off);
            if (lane == 0) out[m * 10 + o] = acc + __ldg(bd + o);
        }
    }
}

// ---------------- launch ----------------
extern "C" void kernel_launch(void* const* d_in, const int* in_sizes, int n_in,
                              void* d_out, int out_size) {
    (void)in_sizes; (void)n_in; (void)out_size;
    const float* x   = (const float*)d_in[0];
    const float* Wi1 = (const float*)d_in[1];
    const float* Wh1 = (const float*)d_in[2];
    const float* b1  = (const float*)d_in[3];
    const float* Wi2 = (const float*)d_in[4];
    const float* Wh2 = (const float*)d_in[5];
    const float* b2  = (const float*)d_in[6];
    const float* Wd  = (const float*)d_in[7];
    const float* bd  = (const float*)d_in[8];
    float* out = (float*)d_out;

    gemmZ1<<<dim3(2, 32), 256>>>(x, Wi1, b1);
    lstmPersist<<<GRIDB, 256>>>(Wh1, Wi2, Wh2, b2, Wd, bd, out);
}

// round 17
// speedup vs baseline: 1.1231x; 1.0678x over previous
#include <cuda_runtime.h>
#include <math.h>
#include <cstdint>

// Problem sizes
#define Bv 256
#define Tv 512
#define Fv 512
#define Hv 512
#define FH 2048
#define NSTEPS 257   // layer1 steps 0..255; layer2 pipelined (batch b = s-1) steps 1..256
#define GRIDB 96

// ---------------- device scratch (no allocations allowed) ----------------
__device__ __align__(16) float gZ1[Bv * FH];     // x[:,T-1,:] @ Wi1 + b1
__device__ __align__(16) float gH1buf[2][Hv];    // double-buffered layer1 hidden
__device__ __align__(16) float gH2buf[2][Hv];    // double-buffered layer2 hidden
__device__ __align__(16) float gH2all[Bv * Hv];  // all layer2 outputs ("last" matrix)
__device__ int g_cnt;                            // grid barrier counter (reset by gemmZ1)

__device__ __forceinline__ float sigf(float x) { return 1.0f / (1.0f + expf(-x)); }

__device__ __forceinline__ int ld_acq(const int* p) {
    int v;
    asm volatile("ld.acquire.gpu.global.b32 %0, [%1];" : "=r"(v) : "l"(p));
    return v;
}
// release reduction: publishes all writes that happened-before (incl. via bar.sync)
__device__ __forceinline__ void red_rel_add(int* p, int v) {
    asm volatile("red.release.gpu.global.add.s32 [%0], %1;" :: "l"(p), "r"(v) : "memory");
}
__device__ __forceinline__ float ldcg(const float* p) {
    float v;
    asm volatile("ld.global.cg.f32 %0, [%1];" : "=f"(v) : "l"(p));
    return v;
}

// ---------------- Phase A: Z1 = x[:,T-1,:] @ Wi1 + b1 (tiled; + counter reset) ----------------
// grid (16 col-tiles of 128, 8 row-tiles of 32), 256 threads. Wi1 L2 traffic 32MB
// (vs 64MB for the streaming variant); x staged through smem per 32-row tile.
__global__ void gemmZ1(const float* __restrict__ x,
                       const float* __restrict__ Wi1,
                       const float* __restrict__ b1) {
    // per-launch barrier-counter reset (stream-ordered before lstmPersist)
    if (blockIdx.x == 0 && blockIdx.y == 0 && threadIdx.x == 0) g_cnt = 0;

    __shared__ __align__(16) float sx[32][33];
    __shared__ __align__(16) float sw[32 * 128];

    const int tid = threadIdx.x;
    const int c0  = blockIdx.x * 128;
    const int b0  = blockIdx.y * 32;
    const int ct  = tid & 31;
    const int bt  = tid >> 5;

    float acc[4][4] = {};

    for (int f0 = 0; f0 < Fv; f0 += 32) {
        {
            int bb = tid >> 3;
            int ff = (tid & 7) * 4;
            const float* xp = x + (size_t)(b0 + bb) * Tv * Fv + (size_t)(Tv - 1) * Fv + f0 + ff;
            float4 v = *(const float4*)xp;
            sx[bb][ff + 0] = v.x; sx[bb][ff + 1] = v.y;
            sx[bb][ff + 2] = v.z; sx[bb][ff + 3] = v.w;
        }
        #pragma unroll
        for (int r = 0; r < 4; r++) {
            int linear = r * 256 + tid;
            int ff = linear >> 5;
            int cc = (linear & 31) * 4;
            float4 v = *(const float4*)(Wi1 + (size_t)(f0 + ff) * FH + c0 + cc);
            *(float4*)&sw[ff * 128 + cc] = v;
        }
        __syncthreads();
        #pragma unroll
        for (int ff = 0; ff < 32; ff++) {
            float4 wv = *(const float4*)&sw[ff * 128 + ct * 4];
            #pragma unroll
            for (int bi = 0; bi < 4; bi++) {
                float xv = sx[bt * 4 + bi][ff];
                acc[bi][0] = fmaf(xv, wv.x, acc[bi][0]);
                acc[bi][1] = fmaf(xv, wv.y, acc[bi][1]);
                acc[bi][2] = fmaf(xv, wv.z, acc[bi][2]);
                acc[bi][3] = fmaf(xv, wv.w, acc[bi][3]);
            }
        }
        __syncthreads();
    }
    const int c = c0 + ct * 4;
    float4 bv = *(const float4*)(b1 + c);
    #pragma unroll
    for (int bi = 0; bi < 4; bi++) {
        int b = b0 + bt * 4 + bi;
        float4 o;
        o.x = acc[bi][0] + bv.x; o.y = acc[bi][1] + bv.y;
        o.z = acc[bi][2] + bv.z; o.w = acc[bi][3] + bv.w;
        *(float4*)&gZ1[(size_t)b * FH + c] = o;
    }
}

// ---------------- Phase B: persistent kernel (exact R16 body — converged design) ----------------
// 96 blocks x 256 threads, all co-resident.
//   Blocks 0..31  : layer1, 16 units each (64 gate-cols), active for s < 256.
//   Blocks 32..95 : layer2, 8 units each (32 gate-cols), active for s >= 1.
// Weights register-resident (32 float4/thread); cell state in owning thread's register.
// Barrier (tied-best R14/R16): bar -> tid0 red.release.gpu.add + ld.acquire spin -> bar.
// Zero-state boundary steps write zeros to smem directly (no init kernel).
__global__ void __launch_bounds__(256, 1) lstmPersist(
    const float* __restrict__ Wh1, const float* __restrict__ Wi2,
    const float* __restrict__ Wh2, const float* __restrict__ b2,
    const float* __restrict__ Wd,  const float* __restrict__ bd,
    float* __restrict__ out)
{
    __shared__ __align__(16) float sH[1024];
    __shared__ __align__(16) float sPart[1024];
    __shared__ float sZ[64];

    const int tid = threadIdx.x;
    const int bx  = blockIdx.x;

    if (bx < 32) {
        // ================= layer 1 =================
        const int u0 = bx * 16;
        const int cg = tid & 15;
        const int ks = tid >> 4;
        const int c0 = cg * 4;
        const int g  = c0 >> 4;
        const int col = g * Hv + u0 + (c0 & 15);
        const int kb  = ks * 32;

        float4 rw[32];
        {
            const float* Wp = Wh1 + (size_t)kb * FH + col;
            #pragma unroll
            for (int j = 0; j < 32; j++)
                rw[j] = *(const float4*)(Wp + (size_t)j * FH);
        }
        float cst = 0.f;   // cell state for unit u0+tid (tid<16)

        for (int s = 0; s < NSTEPS; s++) {
            const int rb = s & 1, wb = rb ^ 1;
            if (s < Bv) {
                if (s > 0) {
                    for (int i = tid; i < Hv; i += 256) sH[i] = ldcg(&gH1buf[rb][i]);
                } else {
                    for (int i = tid; i < Hv; i += 256) sH[i] = 0.f;   // h1[-1] = 0
                }
                __syncthreads();

                float4 a = make_float4(0.f, 0.f, 0.f, 0.f);
                #pragma unroll
                for (int j = 0; j < 32; j++) {
                    float hk = sH[kb + j];
                    a.x = fmaf(hk, rw[j].x, a.x); a.y = fmaf(hk, rw[j].y, a.y);
                    a.z = fmaf(hk, rw[j].z, a.z); a.w = fmaf(hk, rw[j].w, a.w);
                }
                *(float4*)&sPart[ks * 64 + c0] = a;
                __syncthreads();

                if (tid < 64) {
                    float z = 0.f;
                    #pragma unroll
                    for (int r = 0; r < 16; r++) z += sPart[r * 64 + tid];
                    const int gg = tid >> 4;
                    const int cc = gg * Hv + u0 + (tid & 15);
                    sZ[tid] = z + gZ1[(size_t)s * FH + cc];
                }
                __syncthreads();

                if (tid < 16) {
                    const int u = u0 + tid;
                    float zi = sZ[tid], zf = sZ[16 + tid], zg = sZ[32 + tid], zo = sZ[48 + tid];
                    cst = sigf(zf) * cst + sigf(zi) * tanhf(zg);
                    gH1buf[wb][u] = sigf(zo) * tanhf(cst);
                }
            }
            __syncthreads();   // h-stores happen-before tid0's release below
            if (tid == 0) {
                red_rel_add(&g_cnt, 1);
                const int target = GRIDB * (s + 1);
                while (ld_acq(&g_cnt) < target) { }
            }
            __syncthreads();   // release block; next step's ld.cg reads L2
        }
    } else {
        // ================= layer 2 =================
        const int u0 = (bx - 32) * 8;
        const int cg = tid & 7;
        const int ks = tid >> 3;
        const int c0 = cg * 4;
        const int g  = c0 >> 3;
        const int col = g * Hv + u0 + (c0 & 7);
        const int kb  = ks * 32;

        float4 rw[32];
        {
            const float* Wp = (kb < Hv ? Wi2 + (size_t)kb * FH
                                       : Wh2 + (size_t)(kb - Hv) * FH) + col;
            #pragma unroll
            for (int j = 0; j < 32; j++)
                rw[j] = *(const float4*)(Wp + (size_t)j * FH);
        }
        float b2r = 0.f;
        if (tid < 32) {
            const int gg = tid >> 3;
            b2r = b2[gg * Hv + u0 + (tid & 7)];
        }
        float cst = 0.f;   // cell state for unit u0+tid (tid<8)

        for (int s = 0; s < NSTEPS; s++) {
            const int rb = s & 1, wb = rb ^ 1;
            if (s >= 1) {
                for (int i = tid; i < Hv; i += 256) sH[i] = ldcg(&gH1buf[rb][i]);
                if (s >= 2) {
                    for (int i = tid; i < Hv; i += 256) sH[Hv + i] = ldcg(&gH2buf[rb][i]);
                } else {
                    for (int i = tid; i < Hv; i += 256) sH[Hv + i] = 0.f;   // h2[-1] = 0
                }
                __syncthreads();

                float4 a = make_float4(0.f, 0.f, 0.f, 0.f);
                #pragma unroll
                for (int j = 0; j < 32; j++) {
                    float hk = sH[kb + j];
                    a.x = fmaf(hk, rw[j].x, a.x); a.y = fmaf(hk, rw[j].y, a.y);
                    a.z = fmaf(hk, rw[j].z, a.z); a.w = fmaf(hk, rw[j].w, a.w);
                }
                *(float4*)&sPart[ks * 32 + c0] = a;
                __syncthreads();

                if (tid < 32) {
                    float z = 0.f;
                    #pragma unroll
                    for (int r = 0; r < 32; r++) z += sPart[r * 32 + tid];
                    sZ[tid] = z + b2r;
                }
                __syncthreads();

                if (tid < 8) {
                    const int u = u0 + tid;
                    float zi = sZ[tid], zf = sZ[8 + tid], zg = sZ[16 + tid], zo = sZ[24 + tid];
                    cst = sigf(zf) * cst + sigf(zi) * tanhf(zg);
                    float h = sigf(zo) * tanhf(cst);
                    gH2buf[wb][u] = h;
                    gH2all[(size_t)(s - 1) * Hv + u] = h;
                }
            }
            __syncthreads();   // h-stores happen-before tid0's release below
            if (tid == 0) {
                red_rel_add(&g_cnt, 1);
                const int target = GRIDB * (s + 1);
                while (ld_acq(&g_cnt) < target) { }
            }
            __syncthreads();   // release block
        }
    }

    // ================= fused output GEMM: out = gH2all @ Wd + bd =================
    // Final barrier above (acquire of GRIDB*NSTEPS) guarantees gH2all complete & visible.
    const int w    = tid >> 5;
    const int lane = tid & 31;
    for (int m = bx; m < Bv; m += GRIDB) {
        for (int o = w; o < 10; o += 8) {
            float acc = 0.f;
            #pragma unroll
            for (int j = 0; j < 16; j++) {
                int k = lane * 16 + j;
                acc = fmaf(ldcg(&gH2all[(size_t)m * Hv + k]), __ldg(Wd + (size_t)k * 10 + o), acc);
            }
            #pragma unroll
            for (int off = 16; off; off >>= 1)
                acc += __shfl_xor_sync(0xffffffffu, acc, off);
            if (lane == 0) out[m * 10 + o] = acc + __ldg(bd + o);
        }
    }
}

// ---------------- launch ----------------
extern "C" void kernel_launch(void* const* d_in, const int* in_sizes, int n_in,
                              void* d_out, int out_size) {
    (void)in_sizes; (void)n_in; (void)out_size;
    const float* x   = (const float*)d_in[0];
    const float* Wi1 = (const float*)d_in[1];
    const float* Wh1 = (const float*)d_in[2];
    const float* b1  = (const float*)d_in[3];
    const float* Wi2 = (const float*)d_in[4];
    const float* Wh2 = (const float*)d_in[5];
    const float* b2  = (const float*)d_in[6];
    const float* Wd  = (const float*)d_in[7];
    const float* bd  = (const float*)d_in[8];
    float* out = (float*)d_out;

    gemmZ1<<<dim3(16, 8), 256>>>(x, Wi1, b1);
    lstmPersist<<<GRIDB, 256>>>(Wh1, Wi2, Wh2, b2, Wd, bd, out);
}